// round 7
// baseline (speedup 1.0000x reference)
#include <cuda_runtime.h>

#define BATCH 32
#define H 512
#define W 512
#define NSTEPS 10
#define NPIX (H * W)
#define TILE 128
#define SP 152            // smem pitch in floats (fits garbage overreach, %4==0)
#define SROWS 148         // smem rows: local y in [-10, 138)
#define OX 12             // smem col of local x=0 (keeps x%4==0 -> 16B aligned)
#define OY 10             // smem row of local y=0
#define SMEM_BUF (SROWS * SP)
#define NTHREADS 512

__device__ int g_t[BATCH];

// Normalize t into g_t as int32 (handles int64-vs-int32 materialization of the
// jax reference: if int64 little-endian with values in [0,10), all odd 32-bit
// words of the first 128 bytes are zero).
__global__ void prep_t_kernel(const int* __restrict__ traw) {
    int lane = threadIdx.x;  // 0..31
    int w = traw[lane];
    unsigned oddnz = __ballot_sync(0xffffffffu, ((lane & 1) != 0) && (w != 0));
    int v = (oddnz == 0u) ? traw[2 * lane] : w;
    v = min(max(v, 0), NSTEPS);
    g_t[lane] = v;
}

__device__ __forceinline__ float med3(float a, float b, float c) {
    return fmaxf(fminf(a, b), fminf(fmaxf(a, b), c));
}

__device__ __forceinline__ void sort3(float a, float b, float c,
                                      float& lo, float& md, float& hi) {
    float s = fminf(a, b);
    float t = fmaxf(a, b);
    lo = fminf(s, c);
    hi = fmaxf(t, c);
    md = fmaxf(s, fminf(t, c));
}

// Sorted horizontal triples of one input row for 4 output columns x0..x0+3.
// p points at local (row, x=0) inside smem.
__device__ __forceinline__ void load_row_s(const float* __restrict__ p, int x0,
                                           float lo[4], float md[4], float hi[4]) {
    float v0 = p[x0 - 1], v1 = p[x0], v2 = p[x0 + 1],
          v3 = p[x0 + 2], v4 = p[x0 + 3], v5 = p[x0 + 4];
    sort3(v0, v1, v2, lo[0], md[0], hi[0]);
    sort3(v1, v2, v3, lo[1], md[1], hi[1]);
    sort3(v2, v3, v4, lo[2], md[2], hi[2]);
    sort3(v3, v4, v5, lo[3], md[3], hi[3]);
}

// One output row: load row y+1 into slot Cc, combine slots (A,B,Cc), store.
// Template indices keep the rolling arrays in registers.
template <int A, int B, int Cc>
__device__ __forceinline__ void row_step(const float* __restrict__ cb,
                                         float* __restrict__ nb, int y, int x0,
                                         float lo[3][4], float md[3][4], float hi[3][4]) {
    load_row_s(cb + (y + 1) * SP, x0, lo[Cc], md[Cc], hi[Cc]);
    float* orow = nb + y * SP + x0;
#pragma unroll
    for (int q = 0; q < 4; q++) {
        float mn  = fmaxf(fmaxf(lo[A][q], lo[B][q]), lo[Cc][q]);  // max of mins
        float mx  = fminf(fminf(hi[A][q], hi[B][q]), hi[Cc][q]);  // min of maxs
        float mdv = med3(md[A][q], md[B][q], md[Cc][q]);          // med of meds
        orow[q] = med3(mn, mdv, mx);                              // median9
    }
}

extern __shared__ float smem[];

// One CTA = one 128x128 output tile of one batch image; runs all t_b median
// iterations in shared memory (halo 10), writes the final tile to out.
__global__ void __launch_bounds__(NTHREADS, 1) fused_median_kernel(
    const float* __restrict__ x, float* __restrict__ out) {
    float* bufA = smem;
    float* bufB = smem + SMEM_BUF;

    int b = blockIdx.z;
    int k = g_t[b];
    int gx0 = blockIdx.x * TILE, gy0 = blockIdx.y * TILE;
    const float* src = x + (size_t)b * NPIX;

    int tid = threadIdx.x;
    int lane = tid & 31, wrp = tid >> 5;  // 16 warps

    // Load clamped 148x148 tile into bufA: smem rows 0..147 (local y -10..137),
    // smem cols 2..149 (local x -10..137).
    for (int r = wrp; r < SROWS; r += 16) {
        int gy = min(max(gy0 + r - OY, 0), H - 1);
        const float* row = src + gy * W;
        for (int c = 2 + lane; c < 150; c += 32) {
            bufA[r * SP + c] = __ldg(row + min(max(gx0 + c - OX, 0), W - 1));
        }
    }
    __syncthreads();

    float* cur = bufA;
    float* nxt = bufB;
    bool lb = (gx0 == 0), rb = (gx0 + TILE == W);
    bool tb = (gy0 == 0), bb = (gy0 + TILE == H);

    for (int s = 0; s < k; s++) {
        int m = k - 1 - s;  // margin still needed after this step
        int rxlo = lb ? 0 : -m, rxhi = rb ? TILE : TILE + m;
        int rylo = tb ? 0 : -m, ryhi = bb ? TILE : TILE + m;
        int Wr = rxhi - rxlo, Hr = ryhi - rylo;
        int U = (Wr + 3) >> 2;        // 4-wide column units (<= 37)
        int S = NTHREADS / U;         // row strips per column
        int RS = (Hr + S - 1) / S;    // rows per strip

        const float* cb = cur + OY * SP + OX;  // local (0,0)
        float* nb = nxt + OY * SP + OX;

        if (tid < U * S) {
            int ux = tid % U, sy = tid / U;
            int x0 = rxlo + 4 * ux;
            int ylo = rylo + sy * RS;
            int yhi = min(ylo + RS, ryhi);
            if (ylo < yhi) {
                float lo[3][4], md[3][4], hi[3][4];
                load_row_s(cb + (ylo - 1) * SP, x0, lo[0], md[0], hi[0]);
                load_row_s(cb + ylo * SP, x0, lo[1], md[1], hi[1]);
                int y = ylo;
                while (true) {
                    row_step<0, 1, 2>(cb, nb, y, x0, lo, md, hi);
                    if (++y >= yhi) break;
                    row_step<1, 2, 0>(cb, nb, y, x0, lo, md, hi);
                    if (++y >= yhi) break;
                    row_step<2, 0, 1>(cb, nb, y, x0, lo, md, hi);
                    if (++y >= yhi) break;
                }
            }
        }
        __syncthreads();

        // Refresh edge-replicated ring for border tiles (clamp semantics of the
        // *current* iterate). Sources are clamped into the computed region, so
        // corners resolve correctly without an extra barrier.
        if (s + 1 < k) {
            if (lb)
                for (int y = rylo + tid; y < ryhi; y += NTHREADS)
                    nb[y * SP - 1] = nb[y * SP];
            if (rb)
                for (int y = rylo + tid; y < ryhi; y += NTHREADS)
                    nb[y * SP + TILE] = nb[y * SP + TILE - 1];
            if (tb)
                for (int xx = rxlo - 2 + tid; xx < rxhi + 5; xx += NTHREADS) {
                    int sx = min(max(xx, rxlo), rxhi - 1);
                    nb[-SP + xx] = nb[sx];
                }
            if (bb)
                for (int xx = rxlo - 2 + tid; xx < rxhi + 5; xx += NTHREADS) {
                    int sx = min(max(xx, rxlo), rxhi - 1);
                    nb[TILE * SP + xx] = nb[(TILE - 1) * SP + sx];
                }
            if (lb | rb | tb | bb) __syncthreads();
        }
        float* tmp = cur; cur = nxt; nxt = tmp;
    }

    // Store the 128x128 result tile (k==0 -> cur==bufA == clamped copy of x).
    const float* res = cur + OY * SP + OX;
    float* dst = out + (size_t)b * NPIX + (size_t)gy0 * W + gx0;
    for (int r = wrp; r < TILE; r += 16) {
        float4 v = *reinterpret_cast<const float4*>(res + r * SP + lane * 4);
        *reinterpret_cast<float4*>(dst + (size_t)r * W + lane * 4) = v;
    }
}

extern "C" void kernel_launch(void* const* d_in, const int* in_sizes, int n_in,
                              void* d_out, int out_size) {
    const float* x = (const float*)d_in[0];
    const int* traw = (const int*)d_in[1];
    float* out = (float*)d_out;

    size_t smem_bytes = (size_t)2 * SMEM_BUF * sizeof(float);  // 179,968 B
    cudaFuncSetAttribute(fused_median_kernel,
                         cudaFuncAttributeMaxDynamicSharedMemorySize,
                         (int)smem_bytes);

    prep_t_kernel<<<1, 32>>>(traw);

    dim3 grid(W / TILE, H / TILE, BATCH);
    fused_median_kernel<<<grid, NTHREADS, smem_bytes>>>(x, out);
}

// round 9
// speedup vs baseline: 1.3352x; 1.3352x over previous
#include <cuda_runtime.h>

#define BATCH 32
#define H 512
#define W 512
#define NSTEPS 10
#define NPIX (H * W)
#define TW 128            // tile width
#define TH 64             // tile height
#define OX 16             // smem col of local x=0 (mult of 4 -> 16B alignment)
#define OY 10             // smem row of local y=0
#define SP 160            // smem pitch (floats), rows 640B -> float4-aligned
#define SROWS 84          // local y in [-10, 74)
#define SMEM_BUF (SROWS * SP)
#define NTHREADS 512

__device__ int g_t[BATCH];

// Normalize t into g_t as int32 (handles int64-vs-int32 materialization of the
// jax reference: if int64 little-endian with values in [0,10), all odd 32-bit
// words of the first 128 bytes are zero).
__global__ void prep_t_kernel(const int* __restrict__ traw) {
    int lane = threadIdx.x;  // 0..31
    int w = traw[lane];
    unsigned oddnz = __ballot_sync(0xffffffffu, ((lane & 1) != 0) && (w != 0));
    int v = (oddnz == 0u) ? traw[2 * lane] : w;
    v = min(max(v, 0), NSTEPS);
    g_t[lane] = v;
}

__device__ __forceinline__ float med3(float a, float b, float c) {
    return fmaxf(fminf(a, b), fminf(fmaxf(a, b), c));
}

__device__ __forceinline__ void sort3(float a, float b, float c,
                                      float& lo, float& md, float& hi) {
    float s = fminf(a, b);
    float t = fmaxf(a, b);
    lo = fminf(s, c);
    hi = fmaxf(t, c);
    md = fmaxf(s, fminf(t, c));
}

// Sorted horizontal triples of one smem row for 4 output cols x0..x0+3.
// One aligned LDS.128 + two scalar LDS (vs 6 conflicted scalars).
__device__ __forceinline__ void load_row_s(const float* __restrict__ p, int x0,
                                           float lo[4], float md[4], float hi[4]) {
    float4 c = *reinterpret_cast<const float4*>(p + x0);
    float v0 = p[x0 - 1];
    float v5 = p[x0 + 4];
    sort3(v0, c.x, c.y, lo[0], md[0], hi[0]);
    sort3(c.x, c.y, c.z, lo[1], md[1], hi[1]);
    sort3(c.y, c.z, c.w, lo[2], md[2], hi[2]);
    sort3(c.z, c.w, v5, lo[3], md[3], hi[3]);
}

// One output row: load row y+1 into slot Cc, combine (A,B,Cc), STS/STG.128.
template <int A, int B, int Cc>
__device__ __forceinline__ void row_step(const float* __restrict__ cb,
                                         float* __restrict__ orow, int y, int x0,
                                         float lo[3][4], float md[3][4], float hi[3][4]) {
    load_row_s(cb + (y + 1) * SP, x0, lo[Cc], md[Cc], hi[Cc]);
    float r[4];
#pragma unroll
    for (int q = 0; q < 4; q++) {
        float mn  = fmaxf(fmaxf(lo[A][q], lo[B][q]), lo[Cc][q]);  // max of mins
        float mx  = fminf(fminf(hi[A][q], hi[B][q]), hi[Cc][q]);  // min of maxs
        float mdv = med3(md[A][q], md[B][q], md[Cc][q]);          // med of meds
        r[q] = med3(mn, mdv, mx);                                 // median9
    }
    *reinterpret_cast<float4*>(orow) = make_float4(r[0], r[1], r[2], r[3]);
}

// Median-filter region [rxlo,rxhi)x[rylo,ryhi) from smem cb into ob (pitch
// opitch, smem or gmem). rxlo/rxhi multiples of 4.
__device__ __forceinline__ void do_region(const float* __restrict__ cb,
                                          float* __restrict__ ob, int opitch,
                                          int rxlo, int rxhi, int rylo, int ryhi,
                                          int tid) {
    int U = (rxhi - rxlo) >> 2;   // 4-wide units per row (<= 38)
    int S = NTHREADS / U;         // row strips
    if (tid >= U * S) return;
    int Hr = ryhi - rylo;
    int RS = (Hr + S - 1) / S;
    int ux = tid % U, sy = tid / U;
    int x0 = rxlo + 4 * ux;
    int ylo = rylo + sy * RS;
    int yhi = min(ylo + RS, ryhi);
    if (ylo >= yhi) return;

    float lo[3][4], md[3][4], hi[3][4];
    load_row_s(cb + (ylo - 1) * SP, x0, lo[0], md[0], hi[0]);
    load_row_s(cb + ylo * SP, x0, lo[1], md[1], hi[1]);
    float* op = ob + ylo * opitch + x0;
    int y = ylo;
    while (true) {
        row_step<0, 1, 2>(cb, op, y, x0, lo, md, hi);
        if (++y >= yhi) break;
        op += opitch;
        row_step<1, 2, 0>(cb, op, y, x0, lo, md, hi);
        if (++y >= yhi) break;
        op += opitch;
        row_step<2, 0, 1>(cb, op, y, x0, lo, md, hi);
        if (++y >= yhi) break;
        op += opitch;
    }
}

extern __shared__ float smem[];

// One CTA = one 128x64 tile of one batch image; all t_b iterations in smem
// (ping-pong), margin-scheduled; final iteration streams straight to gmem.
__global__ void __launch_bounds__(NTHREADS, 2) fused_median_kernel(
    const float* __restrict__ x, float* __restrict__ out) {
    int b = blockIdx.z;
    int k = g_t[b];
    int gx0 = blockIdx.x * TW, gy0 = blockIdx.y * TH;
    const float* src = x + (size_t)b * NPIX;
    float* dstb = out + (size_t)b * NPIX + gy0 * W + gx0;

    int tid = threadIdx.x, lane = tid & 31, wrp = tid >> 5;  // 16 warps

    if (k == 0) {  // identity: copy tile
        for (int r = wrp; r < TH; r += 16)
            *reinterpret_cast<float4*>(dstb + r * W + lane * 4) =
                *reinterpret_cast<const float4*>(src + (gy0 + r) * W + gx0 + lane * 4);
        return;
    }

    float* bufA = smem;
    float* bufB = smem + SMEM_BUF;

    // Clamped initial load, full pitch (cols 0..159 = local x -16..143,
    // rows 0..83 = local y -10..73). Covers all step-0 reads.
    for (int r = wrp; r < SROWS; r += 16) {
        int gy = min(max(gy0 + r - OY, 0), H - 1);
        const float* rowp = src + gy * W;
        for (int c = lane; c < SP; c += 32)
            bufA[r * SP + c] = __ldg(rowp + min(max(gx0 + c - OX, 0), W - 1));
    }
    __syncthreads();

    bool lb = (gx0 == 0), rb = (gx0 + TW == W);
    bool tb = (gy0 == 0), bb = (gy0 + TH == H);

    float* cur = bufA;
    float* nxt = bufB;
    for (int s = 0; s < k - 1; s++) {
        int m = k - 1 - s;              // margin still needed after this step
        int Xm = (m + 4) & ~3;          // x margin rounded up for alignment;
                                        // Xm >= m+1 keeps contamination < core
        int rxlo = lb ? 0 : -Xm, rxhi = rb ? TW : TW + Xm;
        int rylo = tb ? 0 : -m,  ryhi = bb ? TH : TH + m;
        const float* cb = cur + OY * SP + OX;
        float* nb = nxt + OY * SP + OX;

        do_region(cb, nb, SP, rxlo, rxhi, rylo, ryhi, tid);
        __syncthreads();

        // Edge-replication ring for image-border tiles (clamp semantics of
        // the current iterate). Sources clamp into the computed region.
        if (lb | rb | tb | bb) {
            if (lb)
                for (int y = rylo + tid; y < ryhi; y += NTHREADS)
                    nb[y * SP - 1] = nb[y * SP];
            if (rb)
                for (int y = rylo + tid; y < ryhi; y += NTHREADS)
                    nb[y * SP + TW] = nb[y * SP + TW - 1];
            if (tb)
                for (int xx = rxlo - 1 + tid; xx <= rxhi; xx += NTHREADS) {
                    int sx = min(max(xx, rxlo), rxhi - 1);
                    nb[-SP + xx] = nb[sx];
                }
            if (bb)
                for (int xx = rxlo - 1 + tid; xx <= rxhi; xx += NTHREADS) {
                    int sx = min(max(xx, rxlo), rxhi - 1);
                    nb[TH * SP + xx] = nb[(TH - 1) * SP + sx];
                }
            __syncthreads();
        }
        float* t = cur; cur = nxt; nxt = t;
    }

    // Final iteration: exact 128x64 region, coalesced float4 stores to gmem.
    do_region(cur + OY * SP + OX, dstb, W, 0, TW, 0, TH, tid);
}

extern "C" void kernel_launch(void* const* d_in, const int* in_sizes, int n_in,
                              void* d_out, int out_size) {
    const float* x = (const float*)d_in[0];
    const int* traw = (const int*)d_in[1];
    float* out = (float*)d_out;

    size_t smem_bytes = (size_t)2 * SMEM_BUF * sizeof(float);  // 107,520 B
    cudaFuncSetAttribute(fused_median_kernel,
                         cudaFuncAttributeMaxDynamicSharedMemorySize,
                         (int)smem_bytes);

    prep_t_kernel<<<1, 32>>>(traw);

    dim3 grid(W / TW, H / TH, BATCH);
    fused_median_kernel<<<grid, NTHREADS, smem_bytes>>>(x, out);
}

// round 10
// speedup vs baseline: 1.3956x; 1.0452x over previous
#include <cuda_runtime.h>

#define BATCH 32
#define H 512
#define W 512
#define NSTEPS 10
#define NPIX (H * W)
#define TW 128            // tile width
#define TH 64             // tile height
#define OX 16             // smem col of local x=0 (mult of 4 -> 16B alignment)
#define OY 10             // smem row of local y=0
#define SP 160            // smem pitch (floats), rows 640B -> float4-aligned
#define SROWS 84          // local y in [-10, 74)
#define SMEM_BUF (SROWS * SP)
#define NTHREADS 512

__device__ int g_t[BATCH];
__device__ int g_order[BATCH];  // batches sorted by descending t (LPT schedule)

// Normalize t into g_t as int32 (handles int64-vs-int32 materialization of the
// jax reference: if int64 little-endian with values in [0,10), all odd 32-bit
// words of the first 128 bytes are zero). Also builds the LPT batch order so
// long-running batches launch in wave 1.
__global__ void prep_t_kernel(const int* __restrict__ traw) {
    int lane = threadIdx.x;  // 0..31
    int w = traw[lane];
    unsigned oddnz = __ballot_sync(0xffffffffu, ((lane & 1) != 0) && (w != 0));
    int v = (oddnz == 0u) ? traw[2 * lane] : w;
    v = min(max(v, 0), NSTEPS);
    g_t[lane] = v;

    // rank = position in descending-k order (ties by lane id) -> permutation
    int rank = 0;
#pragma unroll
    for (int j = 0; j < BATCH; j++) {
        int kj = __shfl_sync(0xffffffffu, v, j);
        rank += (kj > v) || (kj == v && j < lane);
    }
    g_order[rank] = lane;
}

__device__ __forceinline__ float med3(float a, float b, float c) {
    return fmaxf(fminf(a, b), fminf(fmaxf(a, b), c));
}

__device__ __forceinline__ void sort3(float a, float b, float c,
                                      float& lo, float& md, float& hi) {
    float s = fminf(a, b);
    float t = fmaxf(a, b);
    lo = fminf(s, c);
    hi = fmaxf(t, c);
    md = fmaxf(s, fminf(t, c));
}

// Sorted horizontal triples of one smem row for 4 output cols x0..x0+3.
// One aligned LDS.128 + two scalar LDS.
__device__ __forceinline__ void load_row_s(const float* __restrict__ p, int x0,
                                           float lo[4], float md[4], float hi[4]) {
    float4 c = *reinterpret_cast<const float4*>(p + x0);
    float v0 = p[x0 - 1];
    float v5 = p[x0 + 4];
    sort3(v0, c.x, c.y, lo[0], md[0], hi[0]);
    sort3(c.x, c.y, c.z, lo[1], md[1], hi[1]);
    sort3(c.y, c.z, c.w, lo[2], md[2], hi[2]);
    sort3(c.z, c.w, v5, lo[3], md[3], hi[3]);
}

// One output row: load row y+1 into slot Cc, combine (A,B,Cc), return median4.
template <int A, int B, int Cc>
__device__ __forceinline__ float4 row_med(const float* __restrict__ cb, int y, int x0,
                                          float lo[3][4], float md[3][4], float hi[3][4]) {
    load_row_s(cb + (y + 1) * SP, x0, lo[Cc], md[Cc], hi[Cc]);
    float r[4];
#pragma unroll
    for (int q = 0; q < 4; q++) {
        float mn  = fmaxf(fmaxf(lo[A][q], lo[B][q]), lo[Cc][q]);  // max of mins
        float mx  = fminf(fminf(hi[A][q], hi[B][q]), hi[Cc][q]);  // min of maxs
        float mdv = med3(md[A][q], md[B][q], md[Cc][q]);          // med of meds
        r[q] = med3(mn, mdv, mx);                                 // median9
    }
    return make_float4(r[0], r[1], r[2], r[3]);
}

// Store one result float4 and any edge-replication ghosts this thread owns
// (producer-writes-ghost: removes the separate ring pass + barrier).
__device__ __forceinline__ void store_row(float* __restrict__ op, int opitch,
                                          float4 r, int y, bool wl, bool wr,
                                          bool tb, bool bb) {
    *reinterpret_cast<float4*>(op) = r;
    if (wl) op[-1] = r.x;
    if (wr) op[4] = r.w;
    if (tb && y == 0) {
        *reinterpret_cast<float4*>(op - opitch) = r;
        if (wl) op[-opitch - 1] = r.x;
        if (wr) op[-opitch + 4] = r.w;
    }
    if (bb && y == TH - 1) {
        *reinterpret_cast<float4*>(op + opitch) = r;
        if (wl) op[opitch - 1] = r.x;
        if (wr) op[opitch + 4] = r.w;
    }
}

// Median-filter region [rxlo,rxhi)x[rylo,ryhi) from smem cb into ob (pitch
// opitch, smem or gmem). rxlo/rxhi multiples of 4. Border flags enable fused
// ghost writes (smem passes only; gmem final pass uses all-false).
__device__ __forceinline__ void do_region(const float* __restrict__ cb,
                                          float* __restrict__ ob, int opitch,
                                          int rxlo, int rxhi, int rylo, int ryhi,
                                          int tid, bool lb, bool rb, bool tb, bool bb) {
    int U = (rxhi - rxlo) >> 2;   // 4-wide units per row (<= 38)
    int S = NTHREADS / U;         // row strips
    if (tid >= U * S) return;
    int Hr = ryhi - rylo;
    int RS = (Hr + S - 1) / S;
    int ux = tid % U, sy = tid / U;
    int x0 = rxlo + 4 * ux;
    int ylo = rylo + sy * RS;
    int yhi = min(ylo + RS, ryhi);
    if (ylo >= yhi) return;
    bool wl = lb && (x0 == rxlo);
    bool wr = rb && (x0 + 4 == rxhi);

    float lo[3][4], md[3][4], hi[3][4];
    load_row_s(cb + (ylo - 1) * SP, x0, lo[0], md[0], hi[0]);
    load_row_s(cb + ylo * SP, x0, lo[1], md[1], hi[1]);
    float* op = ob + ylo * opitch + x0;
    int y = ylo;
    while (true) {
        store_row(op, opitch, row_med<0, 1, 2>(cb, y, x0, lo, md, hi), y, wl, wr, tb, bb);
        if (++y >= yhi) break;
        op += opitch;
        store_row(op, opitch, row_med<1, 2, 0>(cb, y, x0, lo, md, hi), y, wl, wr, tb, bb);
        if (++y >= yhi) break;
        op += opitch;
        store_row(op, opitch, row_med<2, 0, 1>(cb, y, x0, lo, md, hi), y, wl, wr, tb, bb);
        if (++y >= yhi) break;
        op += opitch;
    }
}

extern __shared__ float smem[];

// One CTA = one 128x64 tile of one batch image; all t_b iterations in smem
// (ping-pong), margin-scheduled; final iteration streams straight to gmem.
// Batches are LPT-ordered through g_order via blockIdx.z.
__global__ void __launch_bounds__(NTHREADS, 2) fused_median_kernel(
    const float* __restrict__ x, float* __restrict__ out) {
    int b = g_order[blockIdx.z];
    int k = g_t[b];
    int gx0 = blockIdx.x * TW, gy0 = blockIdx.y * TH;
    const float* src = x + (size_t)b * NPIX;
    float* dstb = out + (size_t)b * NPIX + gy0 * W + gx0;

    int tid = threadIdx.x, lane = tid & 31, wrp = tid >> 5;  // 16 warps

    if (k == 0) {  // identity: copy tile
        for (int r = wrp; r < TH; r += 16)
            *reinterpret_cast<float4*>(dstb + r * W + lane * 4) =
                *reinterpret_cast<const float4*>(src + (gy0 + r) * W + gx0 + lane * 4);
        return;
    }

    float* bufA = smem;
    float* bufB = smem + SMEM_BUF;

    // Clamped initial load, full pitch (cols 0..159 = local x -16..143,
    // rows 0..83 = local y -10..73). Covers all step-0 reads.
    for (int r = wrp; r < SROWS; r += 16) {
        int gy = min(max(gy0 + r - OY, 0), H - 1);
        const float* rowp = src + gy * W;
        for (int c = lane; c < SP; c += 32)
            bufA[r * SP + c] = __ldg(rowp + min(max(gx0 + c - OX, 0), W - 1));
    }
    __syncthreads();

    bool lb = (gx0 == 0), rb = (gx0 + TW == W);
    bool tb = (gy0 == 0), bb = (gy0 + TH == H);

    float* cur = bufA;
    float* nxt = bufB;
    for (int s = 0; s < k - 1; s++) {
        int m = k - 1 - s;              // margin still needed after this step
        int Xm = (m + 4) & ~3;          // x margin rounded up for alignment;
                                        // Xm >= m+1 keeps staleness < core
        int rxlo = lb ? 0 : -Xm, rxhi = rb ? TW : TW + Xm;
        int rylo = tb ? 0 : -m,  ryhi = bb ? TH : TH + m;

        do_region(cur + OY * SP + OX, nxt + OY * SP + OX, SP,
                  rxlo, rxhi, rylo, ryhi, tid, lb, rb, tb, bb);
        __syncthreads();

        float* t = cur; cur = nxt; nxt = t;
    }

    // Final iteration: exact 128x64 region, coalesced float4 stores to gmem.
    do_region(cur + OY * SP + OX, dstb, W, 0, TW, 0, TH, tid,
              false, false, false, false);
}

extern "C" void kernel_launch(void* const* d_in, const int* in_sizes, int n_in,
                              void* d_out, int out_size) {
    const float* x = (const float*)d_in[0];
    const int* traw = (const int*)d_in[1];
    float* out = (float*)d_out;

    size_t smem_bytes = (size_t)2 * SMEM_BUF * sizeof(float);  // 107,520 B
    cudaFuncSetAttribute(fused_median_kernel,
                         cudaFuncAttributeMaxDynamicSharedMemorySize,
                         (int)smem_bytes);

    prep_t_kernel<<<1, 32>>>(traw);

    dim3 grid(W / TW, H / TH, BATCH);
    fused_median_kernel<<<grid, NTHREADS, smem_bytes>>>(x, out);
}

// round 11
// speedup vs baseline: 1.4617x; 1.0473x over previous
#include <cuda_runtime.h>

#define BATCH 32
#define H 512
#define W 512
#define NSTEPS 10
#define NPIX (H * W)
#define TW 128            // tile width
#define TH 64             // tile height
#define OX 12             // smem col of local x=0 (even -> 8B float2 alignment)
#define OY 10             // smem row of local y=0
#define SP 152            // smem pitch (floats), mult of 4
#define SROWS 84          // local y in [-10, 74)
#define SMEM_BUF (SROWS * SP)
#define NTHREADS 512

__device__ int g_t[BATCH];
__device__ int g_order[BATCH];  // batches sorted by descending t (LPT schedule)

// Normalize t into g_t as int32 (handles int64-vs-int32 materialization of the
// jax reference: if int64 little-endian with values in [0,10), all odd 32-bit
// words of the first 128 bytes are zero). Also builds the LPT batch order.
__global__ void prep_t_kernel(const int* __restrict__ traw) {
    int lane = threadIdx.x;  // 0..31
    int w = traw[lane];
    unsigned oddnz = __ballot_sync(0xffffffffu, ((lane & 1) != 0) && (w != 0));
    int v = (oddnz == 0u) ? traw[2 * lane] : w;
    v = min(max(v, 0), NSTEPS);
    g_t[lane] = v;

    int rank = 0;
#pragma unroll
    for (int j = 0; j < BATCH; j++) {
        int kj = __shfl_sync(0xffffffffu, v, j);
        rank += (kj > v) || (kj == v && j < lane);
    }
    g_order[rank] = lane;
}

__device__ __forceinline__ float med3(float a, float b, float c) {
    return fmaxf(fminf(a, b), fminf(fmaxf(a, b), c));
}

__device__ __forceinline__ void sort3(float a, float b, float c,
                                      float& lo, float& md, float& hi) {
    float s = fminf(a, b);
    float t = fmaxf(a, b);
    lo = fminf(s, c);
    hi = fmaxf(t, c);
    md = fmaxf(s, fminf(t, c));
}

// Sorted horizontal triples of one smem row for 2 output cols x0..x0+1.
// offL/offR are per-thread constants implementing the x edge clamp for free.
__device__ __forceinline__ void load_row2(const float* __restrict__ p, int x0,
                                          int offL, int offR,
                                          float lo[2], float md[2], float hi[2]) {
    float2 c = *reinterpret_cast<const float2*>(p + x0);
    float v0 = p[x0 + offL];
    float v3 = p[x0 + offR];
    sort3(v0, c.x, c.y, lo[0], md[0], hi[0]);
    sort3(c.x, c.y, v3, lo[1], md[1], hi[1]);
}

// One output row: load input row yn (pre-clamped) into slot Cc, combine
// (A,B,Cc), store float2. Template indices keep the rotation in registers.
template <int A, int B, int Cc>
__device__ __forceinline__ void row_step(const float* __restrict__ cb,
                                         float* __restrict__ op, int yn, int x0,
                                         int offL, int offR,
                                         float lo[3][2], float md[3][2], float hi[3][2]) {
    load_row2(cb + yn * SP, x0, offL, offR, lo[Cc], md[Cc], hi[Cc]);
    float2 r;
    {
        float mn  = fmaxf(fmaxf(lo[A][0], lo[B][0]), lo[Cc][0]);  // max of mins
        float mx  = fminf(fminf(hi[A][0], hi[B][0]), hi[Cc][0]);  // min of maxs
        float mdv = med3(md[A][0], md[B][0], md[Cc][0]);          // med of meds
        r.x = med3(mn, mdv, mx);                                  // median9
    }
    {
        float mn  = fmaxf(fmaxf(lo[A][1], lo[B][1]), lo[Cc][1]);
        float mx  = fminf(fminf(hi[A][1], hi[B][1]), hi[Cc][1]);
        float mdv = med3(md[A][1], md[B][1], md[Cc][1]);
        r.y = med3(mn, mdv, mx);
    }
    *reinterpret_cast<float2*>(op) = r;
}

// Median-filter region [rxlo,rxhi)x[rylo,ryhi) from smem cb into ob (pitch
// opitch; smem or gmem). rxlo/rxhi even. Image-border clamping is read-side:
// offL/offR (x) and ytop/ycl (y) — no ghost writes, no divergence.
__device__ __forceinline__ void do_region(const float* __restrict__ cb,
                                          float* __restrict__ ob, int opitch,
                                          int rxlo, int rxhi, int rylo, int ryhi,
                                          int tid, bool lb, bool rb, bool tbf, bool bbf) {
    int U = (rxhi - rxlo) >> 1;   // 2-wide units per row (64..74)
    int S = NTHREADS / U;         // row strips (6..8)
    if (tid >= U * S) return;
    int ux = tid % U, sy = tid / U;
    int Hr = ryhi - rylo;
    int ylo = rylo + (sy * Hr) / S;        // balanced heights (diff <= 1)
    int yhi = rylo + ((sy + 1) * Hr) / S;
    if (ylo >= yhi) return;
    int x0 = rxlo + 2 * ux;
    int offL = (lb && x0 == 0) ? 0 : -1;           // x edge clamp, free
    int offR = (rb && x0 + 2 == TW) ? 1 : 2;
    int ycl  = bbf ? (TH - 1) : 0x7fffffff;        // bottom clamp (1 IMNMX/row)
    int ytop = tbf ? 0 : -0x40000000;              // top clamp (prologue only)

    float lo[3][2], md[3][2], hi[3][2];
    load_row2(cb + max(ylo - 1, ytop) * SP, x0, offL, offR, lo[0], md[0], hi[0]);
    load_row2(cb + ylo * SP, x0, offL, offR, lo[1], md[1], hi[1]);
    float* op = ob + ylo * opitch + x0;
    int y = ylo;
    while (true) {
        row_step<0, 1, 2>(cb, op, min(y + 1, ycl), x0, offL, offR, lo, md, hi);
        if (++y >= yhi) break;
        op += opitch;
        row_step<1, 2, 0>(cb, op, min(y + 1, ycl), x0, offL, offR, lo, md, hi);
        if (++y >= yhi) break;
        op += opitch;
        row_step<2, 0, 1>(cb, op, min(y + 1, ycl), x0, offL, offR, lo, md, hi);
        if (++y >= yhi) break;
        op += opitch;
    }
}

extern __shared__ float smem[];

// One CTA = one 128x64 tile of one batch image; all t_b iterations in smem
// (ping-pong), margin-scheduled; final iteration streams straight to gmem.
// Batches are LPT-ordered through g_order via blockIdx.z.
__global__ void __launch_bounds__(NTHREADS, 2) fused_median_kernel(
    const float* __restrict__ x, float* __restrict__ out) {
    int b = g_order[blockIdx.z];
    int k = g_t[b];
    int gx0 = blockIdx.x * TW, gy0 = blockIdx.y * TH;
    const float* src = x + (size_t)b * NPIX;
    float* dstb = out + (size_t)b * NPIX + gy0 * W + gx0;

    int tid = threadIdx.x, lane = tid & 31, wrp = tid >> 5;  // 16 warps

    if (k == 0) {  // identity: copy tile
        for (int r = wrp; r < TH; r += 16)
            *reinterpret_cast<float4*>(dstb + r * W + lane * 4) =
                *reinterpret_cast<const float4*>(src + (gy0 + r) * W + gx0 + lane * 4);
        return;
    }

    float* bufA = smem;
    float* bufB = smem + SMEM_BUF;

    // Clamped initial load, full pitch (cols 0..151 = local x -12..139,
    // rows 0..83 = local y -10..73). Covers all step-0 reads.
    for (int r = wrp; r < SROWS; r += 16) {
        int gy = min(max(gy0 + r - OY, 0), H - 1);
        const float* rowp = src + gy * W;
        for (int c = lane; c < SP; c += 32)
            bufA[r * SP + c] = __ldg(rowp + min(max(gx0 + c - OX, 0), W - 1));
    }
    __syncthreads();

    bool lb = (gx0 == 0), rb = (gx0 + TW == W);
    bool tb = (gy0 == 0), bb = (gy0 + TH == H);

    float* cur = bufA;
    float* nxt = bufB;
    for (int s = 0; s < k - 1; s++) {
        int m = k - 1 - s;              // margin still needed after this step
        int Xm = (m + 2) & ~1;          // even x margin, >= m+1 (stale-proof)
        int rxlo = lb ? 0 : -Xm, rxhi = rb ? TW : TW + Xm;
        int rylo = tb ? 0 : -m,  ryhi = bb ? TH : TH + m;

        do_region(cur + OY * SP + OX, nxt + OY * SP + OX, SP,
                  rxlo, rxhi, rylo, ryhi, tid, lb, rb, tb, bb);
        __syncthreads();

        float* t = cur; cur = nxt; nxt = t;
    }

    // Final iteration: exact 128x64 region, float2 stores to gmem, real
    // border flags (clamping is read-side now).
    do_region(cur + OY * SP + OX, dstb, W, 0, TW, 0, TH, tid, lb, rb, tb, bb);
}

extern "C" void kernel_launch(void* const* d_in, const int* in_sizes, int n_in,
                              void* d_out, int out_size) {
    const float* x = (const float*)d_in[0];
    const int* traw = (const int*)d_in[1];
    float* out = (float*)d_out;

    size_t smem_bytes = (size_t)2 * SMEM_BUF * sizeof(float);  // 102,144 B
    cudaFuncSetAttribute(fused_median_kernel,
                         cudaFuncAttributeMaxDynamicSharedMemorySize,
                         (int)smem_bytes);

    prep_t_kernel<<<1, 32>>>(traw);

    dim3 grid(W / TW, H / TH, BATCH);
    fused_median_kernel<<<grid, NTHREADS, smem_bytes>>>(x, out);
}

// round 12
// speedup vs baseline: 1.5343x; 1.0497x over previous
#include <cuda_runtime.h>

#define BATCH 32
#define H 512
#define W 512
#define NSTEPS 10
#define NPIX (H * W)
#define TW 128            // tile width
#define TH 64             // tile height
#define OX 12             // smem col of local x=0 (even -> 8B float2 alignment)
#define OY 10             // smem row of local y=0
#define SP 152            // smem pitch (floats), mult of 4
#define SROWS 84          // local y in [-10, 74)
#define SMEM_BUF (SROWS * SP)
#define NTHREADS 512

__device__ int g_t[BATCH];
__device__ int g_order[BATCH];  // batches sorted by descending t (LPT schedule)

// Normalize t into g_t as int32 (handles int64-vs-int32 materialization of the
// jax reference: if int64 little-endian with values in [0,10), all odd 32-bit
// words of the first 128 bytes are zero). Also builds the LPT batch order.
__global__ void prep_t_kernel(const int* __restrict__ traw) {
    int lane = threadIdx.x;  // 0..31
    int w = traw[lane];
    unsigned oddnz = __ballot_sync(0xffffffffu, ((lane & 1) != 0) && (w != 0));
    int v = (oddnz == 0u) ? traw[2 * lane] : w;
    v = min(max(v, 0), NSTEPS);
    g_t[lane] = v;

    int rank = 0;
#pragma unroll
    for (int j = 0; j < BATCH; j++) {
        int kj = __shfl_sync(0xffffffffu, v, j);
        rank += (kj > v) || (kj == v && j < lane);
    }
    g_order[rank] = lane;
}

__device__ __forceinline__ float med3(float a, float b, float c) {
    return fmaxf(fminf(a, b), fminf(fmaxf(a, b), c));
}

__device__ __forceinline__ void sort3(float a, float b, float c,
                                      float& lo, float& md, float& hi) {
    float s = fminf(a, b);
    float t = fmaxf(a, b);
    lo = fminf(s, c);
    hi = fmaxf(t, c);
    md = fmaxf(s, fminf(t, c));
}

// Raw 4-value window (x0-1..x0+2, x-clamped via offL/offR) of one smem row.
__device__ __forceinline__ float4 load_raw2(const float* __restrict__ p, int x0,
                                            int offL, int offR) {
    float2 c = *reinterpret_cast<const float2*>(p + x0);
    float4 r;
    r.x = p[x0 + offL];
    r.y = c.x;
    r.z = c.y;
    r.w = p[x0 + offR];
    return r;
}

// Sort a raw window into slot arrays (2 sorted triples).
__device__ __forceinline__ void sort_raw(const float4& v,
                                         float lo[2], float md[2], float hi[2]) {
    sort3(v.x, v.y, v.z, lo[0], md[0], hi[0]);
    sort3(v.y, v.z, v.w, lo[1], md[1], hi[1]);
}

// One output row, software-pipelined: consume prefetched raw into slot Cc,
// ISSUE the next row's loads (pn) early, then combine (A,B,Cc) and store.
// The prefetch LDS latency hides behind ~20 FMNMX of combine work.
template <int A, int B, int Cc>
__device__ __forceinline__ void row_step(const float* __restrict__ pn,
                                         float4& raw, float* __restrict__ op,
                                         int x0, int offL, int offR,
                                         float lo[3][2], float md[3][2], float hi[3][2]) {
    sort_raw(raw, lo[Cc], md[Cc], hi[Cc]);
    float4 nraw = load_raw2(pn, x0, offL, offR);  // independent: issues early
    float2 r;
    {
        float mn  = fmaxf(fmaxf(lo[A][0], lo[B][0]), lo[Cc][0]);  // max of mins
        float mx  = fminf(fminf(hi[A][0], hi[B][0]), hi[Cc][0]);  // min of maxs
        float mdv = med3(md[A][0], md[B][0], md[Cc][0]);          // med of meds
        r.x = med3(mn, mdv, mx);                                  // median9
    }
    {
        float mn  = fmaxf(fmaxf(lo[A][1], lo[B][1]), lo[Cc][1]);
        float mx  = fminf(fminf(hi[A][1], hi[B][1]), hi[Cc][1]);
        float mdv = med3(md[A][1], md[B][1], md[Cc][1]);
        r.y = med3(mn, mdv, mx);
    }
    *reinterpret_cast<float2*>(op) = r;
    raw = nraw;
}

// Median-filter region [rxlo,rxhi)x[rylo,ryhi) from smem cb into ob (pitch
// opitch; smem or gmem). rxlo/rxhi even. Image-border clamping is read-side.
// Over-prefetch past the strip end reads clamped, valid, finite smem rows
// (all rows <= 73 exist) and is discarded.
__device__ __forceinline__ void do_region(const float* __restrict__ cb,
                                          float* __restrict__ ob, int opitch,
                                          int rxlo, int rxhi, int rylo, int ryhi,
                                          int tid, bool lb, bool rb, bool tbf, bool bbf) {
    int U = (rxhi - rxlo) >> 1;   // 2-wide units per row (64..74)
    int S = NTHREADS / U;         // row strips (6..8)
    if (tid >= U * S) return;
    int ux = tid % U, sy = tid / U;
    int Hr = ryhi - rylo;
    int ylo = rylo + (sy * Hr) / S;        // balanced heights (diff <= 1)
    int yhi = rylo + ((sy + 1) * Hr) / S;
    if (ylo >= yhi) return;
    int x0 = rxlo + 2 * ux;
    int offL = (lb && x0 == 0) ? 0 : -1;            // x edge clamp, free
    int offR = (rb && x0 + 2 == TW) ? 1 : 2;
    int yclp = bbf ? (TH - 1) : (SROWS - OY - 1);   // unified read clamp (63/73)
    int ytop = tbf ? 0 : -0x40000000;               // top clamp (prologue only)

    float lo[3][2], md[3][2], hi[3][2];
    sort_raw(load_raw2(cb + max(ylo - 1, ytop) * SP, x0, offL, offR),
             lo[0], md[0], hi[0]);
    sort_raw(load_raw2(cb + ylo * SP, x0, offL, offR),
             lo[1], md[1], hi[1]);
    float4 raw = load_raw2(cb + min(ylo + 1, yclp) * SP, x0, offL, offR);

    float* op = ob + ylo * opitch + x0;
    int y = ylo;
    while (true) {
        row_step<0, 1, 2>(cb + min(y + 2, yclp) * SP, raw, op, x0, offL, offR, lo, md, hi);
        if (++y >= yhi) break;
        op += opitch;
        row_step<1, 2, 0>(cb + min(y + 2, yclp) * SP, raw, op, x0, offL, offR, lo, md, hi);
        if (++y >= yhi) break;
        op += opitch;
        row_step<2, 0, 1>(cb + min(y + 2, yclp) * SP, raw, op, x0, offL, offR, lo, md, hi);
        if (++y >= yhi) break;
        op += opitch;
    }
}

extern __shared__ float smem[];

// One CTA = one 128x64 tile of one batch image; all t_b iterations in smem
// (ping-pong), margin-scheduled; final iteration streams straight to gmem.
// Batches are LPT-ordered through g_order via blockIdx.z.
__global__ void __launch_bounds__(NTHREADS, 2) fused_median_kernel(
    const float* __restrict__ x, float* __restrict__ out) {
    int b = g_order[blockIdx.z];
    int k = g_t[b];
    int gx0 = blockIdx.x * TW, gy0 = blockIdx.y * TH;
    const float* src = x + (size_t)b * NPIX;
    float* dstb = out + (size_t)b * NPIX + gy0 * W + gx0;

    int tid = threadIdx.x, lane = tid & 31, wrp = tid >> 5;  // 16 warps

    if (k == 0) {  // identity: copy tile
        for (int r = wrp; r < TH; r += 16)
            *reinterpret_cast<float4*>(dstb + r * W + lane * 4) =
                *reinterpret_cast<const float4*>(src + (gy0 + r) * W + gx0 + lane * 4);
        return;
    }

    float* bufA = smem;
    float* bufB = smem + SMEM_BUF;

    bool lb = (gx0 == 0), rb = (gx0 + TW == W);
    bool tb = (gy0 == 0), bb = (gy0 + TH == H);

    // Clamped initial load, full pitch (cols 0..151 = local x -12..139,
    // rows 0..83 = local y -10..73). Covers all step-0 reads.
    if (!lb && !rb) {
        // interior-x: no x clamp needed -> coalesced float2 loads
        for (int r = wrp; r < SROWS; r += 16) {
            int gy = min(max(gy0 + r - OY, 0), H - 1);
            const float2* rowp = reinterpret_cast<const float2*>(src + gy * W + gx0 - OX);
            float2* drow = reinterpret_cast<float2*>(bufA + r * SP);
            for (int c = lane; c < SP / 2; c += 32)
                drow[c] = __ldg(rowp + c);
        }
    } else {
        for (int r = wrp; r < SROWS; r += 16) {
            int gy = min(max(gy0 + r - OY, 0), H - 1);
            const float* rowp = src + gy * W;
            for (int c = lane; c < SP; c += 32)
                bufA[r * SP + c] = __ldg(rowp + min(max(gx0 + c - OX, 0), W - 1));
        }
    }
    __syncthreads();

    float* cur = bufA;
    float* nxt = bufB;
    for (int s = 0; s < k - 1; s++) {
        int m = k - 1 - s;              // margin still needed after this step
        int Xm = (m + 2) & ~1;          // even x margin, >= m+1 (stale-proof)
        int rxlo = lb ? 0 : -Xm, rxhi = rb ? TW : TW + Xm;
        int rylo = tb ? 0 : -m,  ryhi = bb ? TH : TH + m;

        do_region(cur + OY * SP + OX, nxt + OY * SP + OX, SP,
                  rxlo, rxhi, rylo, ryhi, tid, lb, rb, tb, bb);
        __syncthreads();

        float* t = cur; cur = nxt; nxt = t;
    }

    // Final iteration: exact 128x64 region, float2 stores to gmem, real
    // border flags (clamping is read-side).
    do_region(cur + OY * SP + OX, dstb, W, 0, TW, 0, TH, tid, lb, rb, tb, bb);
}

extern "C" void kernel_launch(void* const* d_in, const int* in_sizes, int n_in,
                              void* d_out, int out_size) {
    const float* x = (const float*)d_in[0];
    const int* traw = (const int*)d_in[1];
    float* out = (float*)d_out;

    size_t smem_bytes = (size_t)2 * SMEM_BUF * sizeof(float);  // 102,144 B
    cudaFuncSetAttribute(fused_median_kernel,
                         cudaFuncAttributeMaxDynamicSharedMemorySize,
                         (int)smem_bytes);

    prep_t_kernel<<<1, 32>>>(traw);

    dim3 grid(W / TW, H / TH, BATCH);
    fused_median_kernel<<<grid, NTHREADS, smem_bytes>>>(x, out);
}